// round 1
// baseline (speedup 1.0000x reference)
#include <cuda_runtime.h>
#include <math.h>

#define HIDDEN 2048
#define NQ 16
#define NKV 8
#define HD 128
#define SEQ 2048
#define BATCH 2
#define MROWS 4096
#define RANK 8
#define LORA_SC 2.0f
#define SM_SCALE 0.08838834764831845f
#define BMP 132

// ---------------- scratch (device globals: no allocation allowed) -------------
__device__ float g_q[8388608];      // [B][NQ][S][D]
__device__ float g_k[4194304];      // [B][NKV][S][D]
__device__ float g_v[4194304];      // [B][NKV][S][D]
__device__ float g_attn[8388608];   // [B][NQ][S][D]
__device__ float g_tq[MROWS * RANK];
__device__ float g_tk[MROWS * RANK];
__device__ float g_tv[MROWS * RANK];
__device__ float g_to[MROWS * RANK];
__device__ float g_cos[SEQ * 64];
__device__ float g_sin[SEQ * 64];

// ---------------- RoPE tables -------------------------------------------------
__global__ void rope_table_kernel() {
    int idx = blockIdx.x * blockDim.x + threadIdx.x;
    if (idx >= SEQ * 64) return;
    int s = idx >> 6, f = idx & 63;
    double inv = pow(10000.0, -(double)(2 * f) / 128.0);
    double ang = (double)s * inv;
    g_cos[idx] = (float)cos(ang);
    g_sin[idx] = (float)sin(ang);
}

// ---------------- LoRA down-projections (x @ A^T), rank 8 --------------------
__global__ void lora_down_qkv_kernel(const float* __restrict__ x,
                                     const float* __restrict__ qA,
                                     const float* __restrict__ kA,
                                     const float* __restrict__ vA) {
    int m = blockIdx.x, tid = threadIdx.x;
    __shared__ float xs[HIDDEN];
    __shared__ float red[8][24];
    const float4* xr4 = (const float4*)(x + (size_t)m * HIDDEN);
    float4* xs4 = (float4*)xs;
    for (int i = tid; i < HIDDEN / 4; i += 256) xs4[i] = xr4[i];
    __syncthreads();
    float part[24];
#pragma unroll
    for (int j = 0; j < 24; j++) part[j] = 0.f;
    for (int h = tid; h < HIDDEN; h += 256) {
        float xv = xs[h];
#pragma unroll
        for (int r = 0; r < 8; r++) part[r]      += xv * qA[r * HIDDEN + h];
#pragma unroll
        for (int r = 0; r < 8; r++) part[8 + r]  += xv * kA[r * HIDDEN + h];
#pragma unroll
        for (int r = 0; r < 8; r++) part[16 + r] += xv * vA[r * HIDDEN + h];
    }
    int lane = tid & 31, w = tid >> 5;
#pragma unroll
    for (int j = 0; j < 24; j++) {
        float v = part[j];
#pragma unroll
        for (int o = 16; o > 0; o >>= 1) v += __shfl_xor_sync(0xffffffffu, v, o);
        if (lane == 0) red[w][j] = v;
    }
    __syncthreads();
    if (tid < 24) {
        float v = 0.f;
#pragma unroll
        for (int w2 = 0; w2 < 8; w2++) v += red[w2][tid];
        int r = tid & 7;
        if (tid < 8)       g_tq[m * RANK + r] = v;
        else if (tid < 16) g_tk[m * RANK + r] = v;
        else               g_tv[m * RANK + r] = v;
    }
}

__global__ void lora_down_o_kernel(const float* __restrict__ oA) {
    int m = blockIdx.x, tid = threadIdx.x;
    int b = m >> 11, s = m & (SEQ - 1);
    __shared__ float xs[NQ * HD];
    __shared__ float red[8][8];
    for (int f4 = tid; f4 < NQ * HD / 4; f4 += 256) {
        int k0 = f4 * 4;
        int h = k0 >> 7, d = k0 & 127;
        *(float4*)&xs[k0] =
            *(const float4*)&g_attn[(((size_t)(b * NQ + h)) * SEQ + s) * HD + d];
    }
    __syncthreads();
    float part[8];
#pragma unroll
    for (int r = 0; r < 8; r++) part[r] = 0.f;
    for (int k = tid; k < NQ * HD; k += 256) {
        float xv = xs[k];
#pragma unroll
        for (int r = 0; r < 8; r++) part[r] += xv * oA[r * (NQ * HD) + k];
    }
    int lane = tid & 31, w = tid >> 5;
#pragma unroll
    for (int r = 0; r < 8; r++) {
        float v = part[r];
#pragma unroll
        for (int o = 16; o > 0; o >>= 1) v += __shfl_xor_sync(0xffffffffu, v, o);
        if (lane == 0) red[w][r] = v;
    }
    __syncthreads();
    if (tid < 8) {
        float v = 0.f;
#pragma unroll
        for (int w2 = 0; w2 < 8; w2++) v += red[w2][tid];
        g_to[m * RANK + tid] = v;
    }
}

// ---------------- shared GEMM micro-step --------------------------------------
__device__ __forceinline__ void mm_step(const float As[][BMP], const float Ws[][BMP],
                                        float acc[8][8], int ty, int tx, int kk) {
    float4 a0 = *(const float4*)&As[kk][ty * 8];
    float4 a1 = *(const float4*)&As[kk][ty * 8 + 4];
    float4 b0 = *(const float4*)&Ws[kk][tx * 8];
    float4 b1 = *(const float4*)&Ws[kk][tx * 8 + 4];
    float a[8] = {a0.x, a0.y, a0.z, a0.w, a1.x, a1.y, a1.z, a1.w};
    float b[8] = {b0.x, b0.y, b0.z, b0.w, b1.x, b1.y, b1.z, b1.w};
#pragma unroll
    for (int i = 0; i < 8; i++)
#pragma unroll
        for (int j = 0; j < 8; j++) acc[i][j] += a[i] * b[j];
}

// ---------------- QKV projection GEMM (+LoRA up, +RoPE, +BHSD layout) ---------
// C[m,n] = sum_k X[m,k] W[n,k] + 2 * sum_r T[m,r] U[n,r]
template <int ROPE, int NH, int WHICH>
__global__ void __launch_bounds__(256) proj_kernel(const float* __restrict__ X,
                                                   const float* __restrict__ W,
                                                   const float* __restrict__ U) {
    __shared__ float As[16][BMP];
    __shared__ float Ws[16][BMP];
    const float* Tg = (WHICH == 0) ? g_tq : (WHICH == 1) ? g_tk : g_tv;
    float* outp     = (WHICH == 0) ? g_q  : (WHICH == 1) ? g_k  : g_v;
    int tid = threadIdx.x, tx = tid & 15, ty = tid >> 4;
    int n0 = blockIdx.x * 128, m0 = blockIdx.y * 128;
    float acc[8][8];
#pragma unroll
    for (int i = 0; i < 8; i++)
#pragma unroll
        for (int j = 0; j < 8; j++) acc[i][j] = 0.f;

    for (int k0 = 0; k0 < HIDDEN; k0 += 16) {
#pragma unroll
        for (int p = 0; p < 2; p++) {
            int f = tid + p * 256;
            int row = f >> 2, c4 = (f & 3) * 4;
            float4 av = *(const float4*)&X[(size_t)(m0 + row) * HIDDEN + k0 + c4];
            As[c4 + 0][row] = av.x; As[c4 + 1][row] = av.y;
            As[c4 + 2][row] = av.z; As[c4 + 3][row] = av.w;
            float4 wv = *(const float4*)&W[(size_t)(n0 + row) * HIDDEN + k0 + c4];
            Ws[c4 + 0][row] = wv.x; Ws[c4 + 1][row] = wv.y;
            Ws[c4 + 2][row] = wv.z; Ws[c4 + 3][row] = wv.w;
        }
        __syncthreads();
#pragma unroll
        for (int kk = 0; kk < 16; kk++) mm_step(As, Ws, acc, ty, tx, kk);
        __syncthreads();
    }
    // rank-8 LoRA extension: 8 extra K steps through the same pipes
    {
        int row = tid >> 1, c4 = (tid & 1) * 4;
        float4 tv = *(const float4*)&Tg[(m0 + row) * RANK + c4];
        As[c4 + 0][row] = tv.x; As[c4 + 1][row] = tv.y;
        As[c4 + 2][row] = tv.z; As[c4 + 3][row] = tv.w;
        float4 uv = *(const float4*)&U[(n0 + row) * RANK + c4];
        Ws[c4 + 0][row] = uv.x * LORA_SC; Ws[c4 + 1][row] = uv.y * LORA_SC;
        Ws[c4 + 2][row] = uv.z * LORA_SC; Ws[c4 + 3][row] = uv.w * LORA_SC;
        __syncthreads();
#pragma unroll
        for (int kk = 0; kk < 8; kk++) mm_step(As, Ws, acc, ty, tx, kk);
    }
    // epilogue: RoPE + [B][H][S][D] layout store
    int n = n0 + tx * 8;
    int h = n >> 7, d = n & 127;
#pragma unroll
    for (int i = 0; i < 8; i++) {
        int m = m0 + ty * 8 + i;
        int b = m >> 11, s = m & (SEQ - 1);
        float vals[8];
#pragma unroll
        for (int j = 0; j < 8; j++) vals[j] = acc[i][j];
        if (ROPE) {
#pragma unroll
            for (int j = 0; j < 8; j += 2) {
                int f = (d + j) >> 1;
                float c = g_cos[s * 64 + f], sn = g_sin[s * 64 + f];
                float xr = vals[j], xi = vals[j + 1];
                vals[j]     = xr * c - xi * sn;
                vals[j + 1] = xr * sn + xi * c;
            }
        }
        float* op = outp + (((size_t)(b * NH + h)) * SEQ + s) * HD + d;
        *(float4*)op       = make_float4(vals[0], vals[1], vals[2], vals[3]);
        *(float4*)(op + 4) = make_float4(vals[4], vals[5], vals[6], vals[7]);
    }
}

// ---------------- causal flash attention (fp32, GQA 2:1) ----------------------
#define FLASH_SMEM_FLOATS (64 * 128 + 64 * 132 + 64 * 128 + 64 * 68)
__global__ void __launch_bounds__(256) flash_kernel() {
    extern __shared__ float sm[];
    float* Qs = sm;                  // [64][128]
    float* Ks = Qs + 64 * 128;       // [64][132]
    float* Vs = Ks + 64 * 132;       // [64][128]
    float* Ps = Vs + 64 * 128;       // [64][68]
    int tid = threadIdx.x, tx = tid & 15, ty = tid >> 4;
    int qb = blockIdx.x, bh = blockIdx.y;
    int b = bh >> 4, h = bh & 15, kvh = h >> 1;
    const float* Qb = g_q + ((size_t)(b * NQ + h)) * SEQ * HD;
    const float* Kb = g_k + ((size_t)(b * NKV + kvh)) * SEQ * HD;
    const float* Vb = g_v + ((size_t)(b * NKV + kvh)) * SEQ * HD;
    int q0 = qb * 64;

    for (int f = tid; f < 64 * 32; f += 256) {
        int r = f >> 5, c4 = (f & 31) * 4;
        float4 v = *(const float4*)&Qb[(size_t)(q0 + r) * HD + c4];
        v.x *= SM_SCALE; v.y *= SM_SCALE; v.z *= SM_SCALE; v.w *= SM_SCALE;
        *(float4*)&Qs[r * 128 + c4] = v;
    }
    float mrow[4], lrow[4], O[4][8];
#pragma unroll
    for (int i = 0; i < 4; i++) {
        mrow[i] = -1e30f; lrow[i] = 0.f;
#pragma unroll
        for (int j = 0; j < 8; j++) O[i][j] = 0.f;
    }

    for (int kt = 0; kt <= qb; kt++) {
        __syncthreads();
        int k0 = kt * 64;
        for (int f = tid; f < 64 * 32; f += 256) {
            int r = f >> 5, c4 = (f & 31) * 4;
            *(float4*)&Ks[r * 132 + c4] = *(const float4*)&Kb[(size_t)(k0 + r) * HD + c4];
            *(float4*)&Vs[r * 128 + c4] = *(const float4*)&Vb[(size_t)(k0 + r) * HD + c4];
        }
        __syncthreads();

        float sacc[4][4];
#pragma unroll
        for (int i = 0; i < 4; i++)
#pragma unroll
            for (int j = 0; j < 4; j++) sacc[i][j] = 0.f;

        for (int d0 = 0; d0 < 128; d0 += 4) {
            float4 qf[4], kf[4];
#pragma unroll
            for (int i = 0; i < 4; i++) qf[i] = *(float4*)&Qs[(ty * 4 + i) * 128 + d0];
#pragma unroll
            for (int j = 0; j < 4; j++) kf[j] = *(float4*)&Ks[(tx * 4 + j) * 132 + d0];
#pragma unroll
            for (int i = 0; i < 4; i++)
#pragma unroll
                for (int j = 0; j < 4; j++)
                    sacc[i][j] += qf[i].x * kf[j].x + qf[i].y * kf[j].y +
                                  qf[i].z * kf[j].z + qf[i].w * kf[j].w;
        }
        if (kt == qb) {
#pragma unroll
            for (int i = 0; i < 4; i++)
#pragma unroll
                for (int j = 0; j < 4; j++)
                    if (tx * 4 + j > ty * 4 + i) sacc[i][j] = -1e30f;
        }
#pragma unroll
        for (int i = 0; i < 4; i++) {
            float mx = fmaxf(fmaxf(sacc[i][0], sacc[i][1]), fmaxf(sacc[i][2], sacc[i][3]));
#pragma unroll
            for (int o = 8; o > 0; o >>= 1)
                mx = fmaxf(mx, __shfl_xor_sync(0xffffffffu, mx, o, 16));
            float mnew = fmaxf(mrow[i], mx);
            float corr = __expf(mrow[i] - mnew);
            float rs = 0.f;
#pragma unroll
            for (int j = 0; j < 4; j++) {
                float p = __expf(sacc[i][j] - mnew);
                sacc[i][j] = p;
                rs += p;
            }
#pragma unroll
            for (int o = 8; o > 0; o >>= 1)
                rs += __shfl_xor_sync(0xffffffffu, rs, o, 16);
            lrow[i] = lrow[i] * corr + rs;
            mrow[i] = mnew;
#pragma unroll
            for (int j = 0; j < 8; j++) O[i][j] *= corr;
            *(float4*)&Ps[(ty * 4 + i) * 68 + tx * 4] =
                make_float4(sacc[i][0], sacc[i][1], sacc[i][2], sacc[i][3]);
        }
        __syncthreads();
        for (int kk = 0; kk < 64; kk += 4) {
            float4 p4[4];
#pragma unroll
            for (int i = 0; i < 4; i++) p4[i] = *(float4*)&Ps[(ty * 4 + i) * 68 + kk];
#pragma unroll
            for (int u = 0; u < 4; u++) {
                float4 va = *(float4*)&Vs[(kk + u) * 128 + tx * 8];
                float4 vb = *(float4*)&Vs[(kk + u) * 128 + tx * 8 + 4];
#pragma unroll
                for (int i = 0; i < 4; i++) {
                    float pv = (u == 0) ? p4[i].x : (u == 1) ? p4[i].y
                             : (u == 2) ? p4[i].z : p4[i].w;
                    O[i][0] += pv * va.x; O[i][1] += pv * va.y;
                    O[i][2] += pv * va.z; O[i][3] += pv * va.w;
                    O[i][4] += pv * vb.x; O[i][5] += pv * vb.y;
                    O[i][6] += pv * vb.z; O[i][7] += pv * vb.w;
                }
            }
        }
    }
    float* Ob = g_attn + ((size_t)(b * NQ + h)) * SEQ * HD;
#pragma unroll
    for (int i = 0; i < 4; i++) {
        float inv = 1.f / lrow[i];
        int r = q0 + ty * 4 + i;
        float* op = Ob + (size_t)r * HD + tx * 8;
        *(float4*)op       = make_float4(O[i][0] * inv, O[i][1] * inv, O[i][2] * inv, O[i][3] * inv);
        *(float4*)(op + 4) = make_float4(O[i][4] * inv, O[i][5] * inv, O[i][6] * inv, O[i][7] * inv);
    }
}

// ---------------- output projection GEMM (+LoRA up) ---------------------------
__global__ void __launch_bounds__(256) oproj_kernel(const float* __restrict__ Wo,
                                                    const float* __restrict__ oB,
                                                    float* __restrict__ out) {
    __shared__ float As[16][BMP];
    __shared__ float Ws[16][BMP];
    int tid = threadIdx.x, tx = tid & 15, ty = tid >> 4;
    int n0 = blockIdx.x * 128, m0 = blockIdx.y * 128;
    float acc[8][8];
#pragma unroll
    for (int i = 0; i < 8; i++)
#pragma unroll
        for (int j = 0; j < 8; j++) acc[i][j] = 0.f;

    for (int k0 = 0; k0 < NQ * HD; k0 += 16) {
#pragma unroll
        for (int p = 0; p < 2; p++) {
            int f = tid + p * 256;
            int row = f >> 2, c4 = (f & 3) * 4;
            int m = m0 + row;
            int b = m >> 11, s = m & (SEQ - 1);
            int kf = k0 + c4;
            int h = kf >> 7, d = kf & 127;
            float4 av = *(const float4*)&g_attn[(((size_t)(b * NQ + h)) * SEQ + s) * HD + d];
            As[c4 + 0][row] = av.x; As[c4 + 1][row] = av.y;
            As[c4 + 2][row] = av.z; As[c4 + 3][row] = av.w;
            float4 wv = *(const float4*)&Wo[(size_t)(n0 + row) * (NQ * HD) + k0 + c4];
            Ws[c4 + 0][row] = wv.x; Ws[c4 + 1][row] = wv.y;
            Ws[c4 + 2][row] = wv.z; Ws[c4 + 3][row] = wv.w;
        }
        __syncthreads();
#pragma unroll
        for (int kk = 0; kk < 16; kk++) mm_step(As, Ws, acc, ty, tx, kk);
        __syncthreads();
    }
    {
        int row = tid >> 1, c4 = (tid & 1) * 4;
        float4 tv = *(const float4*)&g_to[(m0 + row) * RANK + c4];
        As[c4 + 0][row] = tv.x; As[c4 + 1][row] = tv.y;
        As[c4 + 2][row] = tv.z; As[c4 + 3][row] = tv.w;
        float4 uv = *(const float4*)&oB[(n0 + row) * RANK + c4];
        Ws[c4 + 0][row] = uv.x * LORA_SC; Ws[c4 + 1][row] = uv.y * LORA_SC;
        Ws[c4 + 2][row] = uv.z * LORA_SC; Ws[c4 + 3][row] = uv.w * LORA_SC;
        __syncthreads();
#pragma unroll
        for (int kk = 0; kk < 8; kk++) mm_step(As, Ws, acc, ty, tx, kk);
    }
#pragma unroll
    for (int i = 0; i < 8; i++) {
        int m = m0 + ty * 8 + i;
        float* op = out + (size_t)m * HIDDEN + n0 + tx * 8;
        *(float4*)op       = make_float4(acc[i][0], acc[i][1], acc[i][2], acc[i][3]);
        *(float4*)(op + 4) = make_float4(acc[i][4], acc[i][5], acc[i][6], acc[i][7]);
    }
}

// ---------------- launch ------------------------------------------------------
extern "C" void kernel_launch(void* const* d_in, const int* in_sizes, int n_in,
                              void* d_out, int out_size) {
    const float* x  = (const float*)d_in[0];
    const float* Wq = (const float*)d_in[1];
    const float* Wk = (const float*)d_in[2];
    const float* Wv = (const float*)d_in[3];
    const float* Wo = (const float*)d_in[4];
    const float* qA = (const float*)d_in[5];
    const float* qB = (const float*)d_in[6];
    const float* kA = (const float*)d_in[7];
    const float* kB = (const float*)d_in[8];
    const float* vA = (const float*)d_in[9];
    const float* vB = (const float*)d_in[10];
    const float* oA = (const float*)d_in[11];
    const float* oB = (const float*)d_in[12];
    float* out = (float*)d_out;

    rope_table_kernel<<<512, 256>>>();
    lora_down_qkv_kernel<<<MROWS, 256>>>(x, qA, kA, vA);
    proj_kernel<1, NQ, 0><<<dim3(16, 32), 256>>>(x, Wq, qB);
    proj_kernel<1, NKV, 1><<<dim3(8, 32), 256>>>(x, Wk, kB);
    proj_kernel<0, NKV, 2><<<dim3(8, 32), 256>>>(x, Wv, vB);

    cudaFuncSetAttribute(flash_kernel, cudaFuncAttributeMaxDynamicSharedMemorySize,
                         FLASH_SMEM_FLOATS * 4);
    flash_kernel<<<dim3(SEQ / 64, BATCH * NQ), 256, FLASH_SMEM_FLOATS * 4>>>();

    lora_down_o_kernel<<<MROWS, 256>>>(oA);
    oproj_kernel<<<dim3(16, 32), 256>>>(Wo, oB, out);
}

// round 2
// speedup vs baseline: 2.2792x; 2.2792x over previous
#include <cuda_runtime.h>
#include <math.h>
#include <stdint.h>

#define HIDDEN 2048
#define NQ 16
#define NKV 8
#define HD 128
#define SEQ 2048
#define BATCH 2
#define MROWS 4096
#define RANK 8
#define LORA_SC 2.0f
#define SM_SCALE 0.08838834764831845f

// ---------------- scratch (device globals: no allocation allowed) -------------
__device__ float g_q[8388608];      // [B][NQ][S][D]
__device__ float g_k[4194304];      // [B][NKV][S][D]
__device__ float g_v[4194304];      // [B][NKV][S][D]
__device__ float g_attn[8388608];   // [B][NQ][S][D]
__device__ float g_tq[MROWS * RANK];
__device__ float g_tk[MROWS * RANK];
__device__ float g_tv[MROWS * RANK];
__device__ float g_to[MROWS * RANK];
__device__ float g_cos[SEQ * 64];
__device__ float g_sin[SEQ * 64];

// ---------------- helpers -----------------------------------------------------
__device__ __forceinline__ uint32_t f2tf(float x) {
    uint32_t r;
    asm("cvt.rna.tf32.f32 %0, %1;" : "=r"(r) : "f"(x));
    return r;
}

__device__ __forceinline__ void mma8(float* c, uint32_t a0, uint32_t a1,
                                     uint32_t a2, uint32_t a3,
                                     uint32_t b0, uint32_t b1) {
    asm volatile(
        "mma.sync.aligned.m16n8k8.row.col.f32.tf32.tf32.f32 "
        "{%0,%1,%2,%3}, {%4,%5,%6,%7}, {%8,%9}, {%0,%1,%2,%3};\n"
        : "+f"(c[0]), "+f"(c[1]), "+f"(c[2]), "+f"(c[3])
        : "r"(a0), "r"(a1), "r"(a2), "r"(a3), "r"(b0), "r"(b1));
}

// pair permutation within a k8 block: cols (t, t+4) become adjacent words (2t, 2t+1)
__device__ __forceinline__ int P8f(int c) { return ((c & 3) << 1) | ((c >> 2) & 1); }
__device__ __forceinline__ int PERMf(int c) { return (c & ~7) | P8f(c & 7); }

// ---------------- RoPE tables -------------------------------------------------
__global__ void rope_table_kernel() {
    int idx = blockIdx.x * blockDim.x + threadIdx.x;
    if (idx >= SEQ * 64) return;
    int s = idx >> 6, f = idx & 63;
    double inv = pow(10000.0, -(double)(2 * f) / 128.0);
    double ang = (double)s * inv;
    g_cos[idx] = (float)cos(ang);
    g_sin[idx] = (float)sin(ang);
}

// ---------------- LoRA down-projections (x @ A^T), rank 8 --------------------
__global__ void lora_down_qkv_kernel(const float* __restrict__ x,
                                     const float* __restrict__ qA,
                                     const float* __restrict__ kA,
                                     const float* __restrict__ vA) {
    int m = blockIdx.x, tid = threadIdx.x;
    __shared__ float xs[HIDDEN];
    __shared__ float red[8][24];
    const float4* xr4 = (const float4*)(x + (size_t)m * HIDDEN);
    float4* xs4 = (float4*)xs;
    for (int i = tid; i < HIDDEN / 4; i += 256) xs4[i] = xr4[i];
    __syncthreads();
    float part[24];
#pragma unroll
    for (int j = 0; j < 24; j++) part[j] = 0.f;
    for (int h = tid; h < HIDDEN; h += 256) {
        float xv = xs[h];
#pragma unroll
        for (int r = 0; r < 8; r++) part[r]      += xv * qA[r * HIDDEN + h];
#pragma unroll
        for (int r = 0; r < 8; r++) part[8 + r]  += xv * kA[r * HIDDEN + h];
#pragma unroll
        for (int r = 0; r < 8; r++) part[16 + r] += xv * vA[r * HIDDEN + h];
    }
    int lane = tid & 31, w = tid >> 5;
#pragma unroll
    for (int j = 0; j < 24; j++) {
        float v = part[j];
#pragma unroll
        for (int o = 16; o > 0; o >>= 1) v += __shfl_xor_sync(0xffffffffu, v, o);
        if (lane == 0) red[w][j] = v;
    }
    __syncthreads();
    if (tid < 24) {
        float v = 0.f;
#pragma unroll
        for (int w2 = 0; w2 < 8; w2++) v += red[w2][tid];
        int r = tid & 7;
        if (tid < 8)       g_tq[m * RANK + r] = v;
        else if (tid < 16) g_tk[m * RANK + r] = v;
        else               g_tv[m * RANK + r] = v;
    }
}

__global__ void lora_down_o_kernel(const float* __restrict__ oA) {
    int m = blockIdx.x, tid = threadIdx.x;
    int b = m >> 11, s = m & (SEQ - 1);
    __shared__ float xs[NQ * HD];
    __shared__ float red[8][8];
    for (int f4 = tid; f4 < NQ * HD / 4; f4 += 256) {
        int k0 = f4 * 4;
        int h = k0 >> 7, d = k0 & 127;
        *(float4*)&xs[k0] =
            *(const float4*)&g_attn[(((size_t)(b * NQ + h)) * SEQ + s) * HD + d];
    }
    __syncthreads();
    float part[8];
#pragma unroll
    for (int r = 0; r < 8; r++) part[r] = 0.f;
    for (int k = tid; k < NQ * HD; k += 256) {
        float xv = xs[k];
#pragma unroll
        for (int r = 0; r < 8; r++) part[r] += xv * oA[r * (NQ * HD) + k];
    }
    int lane = tid & 31, w = tid >> 5;
#pragma unroll
    for (int r = 0; r < 8; r++) {
        float v = part[r];
#pragma unroll
        for (int o = 16; o > 0; o >>= 1) v += __shfl_xor_sync(0xffffffffu, v, o);
        if (lane == 0) red[w][r] = v;
    }
    __syncthreads();
    if (tid < 8) {
        float v = 0.f;
#pragma unroll
        for (int w2 = 0; w2 < 8; w2++) v += red[w2][tid];
        g_to[m * RANK + tid] = v;
    }
}

// ---------------- unified tf32 GEMM (Q/K/V/O projections) ---------------------
// C[m,n] = sum_k A[m,k] W[n,k] + 2 * sum_r T[m,r] U[n,r]
// WHICH: 0=Q(rope), 1=K(rope), 2=V, 3=O-proj (gathers A from g_attn, writes Out)
#define TS 24   // smem row stride in words (24 mod 32 == 24 -> rows 0..3 bank-disjoint)
#define GEMM_SMEM (4 * 128 * TS * 4)

template <int WHICH>
__device__ __forceinline__ float4 ldA(const float* __restrict__ Xsrc, int m, int kf) {
    if (WHICH == 3) {
        int b = m >> 11, s = m & 2047, h = kf >> 7, d = kf & 127;
        return *(const float4*)&g_attn[(((size_t)(b * NQ + h)) * SEQ + s) * HD + d];
    }
    return *(const float4*)&Xsrc[(size_t)m * HIDDEN + kf];
}

__device__ __forceinline__ void stTile(uint32_t* T, int row, int c4, float4 v) {
    T[row * TS + PERMf(c4 + 0)] = f2tf(v.x);
    T[row * TS + PERMf(c4 + 1)] = f2tf(v.y);
    T[row * TS + PERMf(c4 + 2)] = f2tf(v.z);
    T[row * TS + PERMf(c4 + 3)] = f2tf(v.w);
}

template <int WHICH, int NH>
__global__ void __launch_bounds__(256) gemm_kernel(const float* __restrict__ Xsrc,
                                                   const float* __restrict__ W,
                                                   const float* __restrict__ U,
                                                   float* __restrict__ Out) {
    extern __shared__ uint32_t sm[];
    uint32_t* As = sm;                  // [2][128*TS]
    uint32_t* Bs = sm + 2 * 128 * TS;   // [2][128*TS]
    const int tid = threadIdx.x, lane = tid & 31, wid = tid >> 5;
    const int wm = (wid & 3) * 32, wn = (wid >> 2) * 64;
    const int g = lane >> 2, tig = lane & 3;
    const int m0 = blockIdx.y * 128, n0 = blockIdx.x * 128;
    const float* Tg = (WHICH == 0) ? g_tq : (WHICH == 1) ? g_tk
                    : (WHICH == 2) ? g_tv : g_to;

    float acc[2][8][4];
#pragma unroll
    for (int a = 0; a < 2; a++)
#pragma unroll
        for (int b2 = 0; b2 < 8; b2++)
#pragma unroll
            for (int c = 0; c < 4; c++) acc[a][b2][c] = 0.f;

    const int row_ = tid >> 2, c4_ = (tid & 3) * 4;
    float4 ra[2], rb[2];

    // preload chunk 0 into buffer 0
    ra[0] = ldA<WHICH>(Xsrc, m0 + row_, c4_);
    ra[1] = ldA<WHICH>(Xsrc, m0 + row_ + 64, c4_);
    rb[0] = *(const float4*)&W[(size_t)(n0 + row_) * HIDDEN + c4_];
    rb[1] = *(const float4*)&W[(size_t)(n0 + row_ + 64) * HIDDEN + c4_];
    stTile(As, row_, c4_, ra[0]);
    stTile(As, row_ + 64, c4_, ra[1]);
    stTile(Bs, row_, c4_, rb[0]);
    stTile(Bs, row_ + 64, c4_, rb[1]);
    __syncthreads();

    for (int kc = 0; kc < HIDDEN / 16; kc++) {
        const uint32_t* Ab = As + (kc & 1) * (128 * TS);
        const uint32_t* Bb = Bs + (kc & 1) * (128 * TS);
        if (kc + 1 < HIDDEN / 16) {
            int kf = (kc + 1) * 16 + c4_;
            ra[0] = ldA<WHICH>(Xsrc, m0 + row_, kf);
            ra[1] = ldA<WHICH>(Xsrc, m0 + row_ + 64, kf);
            rb[0] = *(const float4*)&W[(size_t)(n0 + row_) * HIDDEN + kf];
            rb[1] = *(const float4*)&W[(size_t)(n0 + row_ + 64) * HIDDEN + kf];
        }
#pragma unroll
        for (int kk = 0; kk < 16; kk += 8) {
            uint2 aA0 = *(const uint2*)&Ab[(wm + g) * TS + kk + 2 * tig];
            uint2 aB0 = *(const uint2*)&Ab[(wm + g + 8) * TS + kk + 2 * tig];
            uint2 aA1 = *(const uint2*)&Ab[(wm + 16 + g) * TS + kk + 2 * tig];
            uint2 aB1 = *(const uint2*)&Ab[(wm + 16 + g + 8) * TS + kk + 2 * tig];
#pragma unroll
            for (int ni = 0; ni < 8; ni++) {
                uint2 bb = *(const uint2*)&Bb[(wn + ni * 8 + g) * TS + kk + 2 * tig];
                mma8(acc[0][ni], aA0.x, aB0.x, aA0.y, aB0.y, bb.x, bb.y);
                mma8(acc[1][ni], aA1.x, aB1.x, aA1.y, aB1.y, bb.x, bb.y);
            }
        }
        __syncthreads();
        if (kc + 1 < HIDDEN / 16) {
            uint32_t* An = As + ((kc + 1) & 1) * (128 * TS);
            uint32_t* Bn = Bs + ((kc + 1) & 1) * (128 * TS);
            stTile(An, row_, c4_, ra[0]);
            stTile(An, row_ + 64, c4_, ra[1]);
            stTile(Bn, row_, c4_, rb[0]);
            stTile(Bn, row_ + 64, c4_, rb[1]);
        }
        __syncthreads();
    }

    // LoRA rank-8 tail (one k8 step) staged into buffer 0
    {
        int row = tid >> 1, c4 = (tid & 1) * 4;
        float4 tv = *(const float4*)&Tg[(m0 + row) * RANK + c4];
        As[row * TS + P8f(c4 + 0)] = f2tf(tv.x);
        As[row * TS + P8f(c4 + 1)] = f2tf(tv.y);
        As[row * TS + P8f(c4 + 2)] = f2tf(tv.z);
        As[row * TS + P8f(c4 + 3)] = f2tf(tv.w);
        float4 uv = *(const float4*)&U[(n0 + row) * RANK + c4];
        Bs[row * TS + P8f(c4 + 0)] = f2tf(uv.x * LORA_SC);
        Bs[row * TS + P8f(c4 + 1)] = f2tf(uv.y * LORA_SC);
        Bs[row * TS + P8f(c4 + 2)] = f2tf(uv.z * LORA_SC);
        Bs[row * TS + P8f(c4 + 3)] = f2tf(uv.w * LORA_SC);
    }
    __syncthreads();
    {
        uint2 aA0 = *(const uint2*)&As[(wm + g) * TS + 2 * tig];
        uint2 aB0 = *(const uint2*)&As[(wm + g + 8) * TS + 2 * tig];
        uint2 aA1 = *(const uint2*)&As[(wm + 16 + g) * TS + 2 * tig];
        uint2 aB1 = *(const uint2*)&As[(wm + 16 + g + 8) * TS + 2 * tig];
#pragma unroll
        for (int ni = 0; ni < 8; ni++) {
            uint2 bb = *(const uint2*)&Bs[(wn + ni * 8 + g) * TS + 2 * tig];
            mma8(acc[0][ni], aA0.x, aB0.x, aA0.y, aB0.y, bb.x, bb.y);
            mma8(acc[1][ni], aA1.x, aB1.x, aA1.y, aB1.y, bb.x, bb.y);
        }
    }

    // epilogue: optional RoPE + store
#pragma unroll
    for (int mi = 0; mi < 2; mi++) {
#pragma unroll
        for (int rr = 0; rr < 2; rr++) {
            int m = m0 + wm + mi * 16 + g + rr * 8;
            int s = m & 2047, b = m >> 11;
#pragma unroll
            for (int ni = 0; ni < 8; ni++) {
                int n = n0 + wn + ni * 8 + 2 * tig;
                float v0 = acc[mi][ni][rr * 2 + 0];
                float v1 = acc[mi][ni][rr * 2 + 1];
                if (WHICH <= 1) {
                    int f = (n & 127) >> 1;
                    float c = g_cos[s * 64 + f], sn = g_sin[s * 64 + f];
                    float t0 = v0 * c - v1 * sn;
                    v1 = v0 * sn + v1 * c;
                    v0 = t0;
                }
                if (WHICH == 3) {
                    *(float2*)&Out[(size_t)m * HIDDEN + n] = make_float2(v0, v1);
                } else {
                    float* dst = (WHICH == 0) ? g_q : (WHICH == 1) ? g_k : g_v;
                    int h = n >> 7, d = n & 127;
                    *(float2*)&dst[(((size_t)(b * NH + h)) * SEQ + s) * HD + d] =
                        make_float2(v0, v1);
                }
            }
        }
    }
}

// ---------------- tensor-core causal flash attention (tf32, GQA 2:1) ----------
#define QS_STRIDE 136
#define KS_STRIDE 136
#define VS_STRIDE 72
#define PS_STRIDE 72
#define FLASH_SMEM ((128 * QS_STRIDE + 64 * KS_STRIDE + 128 * VS_STRIDE + 128 * PS_STRIDE) * 4)

__global__ void __launch_bounds__(256) flash_kernel() {
    extern __shared__ uint32_t sm[];
    uint32_t* Qs = sm;                      // [128][QS_STRIDE] (d pair-permuted)
    uint32_t* Ks = Qs + 128 * QS_STRIDE;    // [64][KS_STRIDE]  (d pair-permuted)
    uint32_t* Vs = Ks + 64 * KS_STRIDE;     // [128(d)][VS_STRIDE] (kv pair-permuted)
    uint32_t* Ps = Vs + 128 * VS_STRIDE;    // [128][PS_STRIDE] (kv pair-permuted)
    int tid = threadIdx.x, lane = tid & 31, wid = tid >> 5;
    int g = lane >> 2, tig = lane & 3;
    int qb = blockIdx.x, bh = blockIdx.y;
    int b = bh >> 4, h = bh & 15, kvh = h >> 1;
    const float* Qb = g_q + ((size_t)(b * NQ + h)) * SEQ * HD;
    const float* Kb = g_k + ((size_t)(b * NKV + kvh)) * SEQ * HD;
    const float* Vb = g_v + ((size_t)(b * NKV + kvh)) * SEQ * HD;
    int q0 = qb * 128;
    int rb0 = wid * 16;

    // load Q once (pre-scaled, tf32, permuted)
    for (int f = tid; f < 128 * 32; f += 256) {
        int r = f >> 5, c4 = (f & 31) << 2;
        float4 v = *(const float4*)&Qb[(size_t)(q0 + r) * HD + c4];
        Qs[r * QS_STRIDE + PERMf(c4 + 0)] = f2tf(v.x * SM_SCALE);
        Qs[r * QS_STRIDE + PERMf(c4 + 1)] = f2tf(v.y * SM_SCALE);
        Qs[r * QS_STRIDE + PERMf(c4 + 2)] = f2tf(v.z * SM_SCALE);
        Qs[r * QS_STRIDE + PERMf(c4 + 3)] = f2tf(v.w * SM_SCALE);
    }

    float O[16][4];
#pragma unroll
    for (int i = 0; i < 16; i++)
#pragma unroll
        for (int j = 0; j < 4; j++) O[i][j] = 0.f;
    float mrow[2] = {-1e30f, -1e30f}, lrow[2] = {0.f, 0.f};

    int ktmax = 2 * qb + 1;
    for (int kt = 0; kt <= ktmax; kt++) {
        __syncthreads();
        int k0 = kt * 64;
        for (int f = tid; f < 64 * 32; f += 256) {
            int r = f >> 5, c4 = (f & 31) << 2;
            float4 kv = *(const float4*)&Kb[(size_t)(k0 + r) * HD + c4];
            Ks[r * KS_STRIDE + PERMf(c4 + 0)] = f2tf(kv.x);
            Ks[r * KS_STRIDE + PERMf(c4 + 1)] = f2tf(kv.y);
            Ks[r * KS_STRIDE + PERMf(c4 + 2)] = f2tf(kv.z);
            Ks[r * KS_STRIDE + PERMf(c4 + 3)] = f2tf(kv.w);
            float4 vv = *(const float4*)&Vb[(size_t)(k0 + r) * HD + c4];
            int pc = (r & ~7) | P8f(r & 7);
            Vs[(c4 + 0) * VS_STRIDE + pc] = f2tf(vv.x);
            Vs[(c4 + 1) * VS_STRIDE + pc] = f2tf(vv.y);
            Vs[(c4 + 2) * VS_STRIDE + pc] = f2tf(vv.z);
            Vs[(c4 + 3) * VS_STRIDE + pc] = f2tf(vv.w);
        }
        __syncthreads();

        // S = Q @ K^T  (warp rows rb0..rb0+15, 8 n8-tiles over kv)
        float sacc[8][4];
#pragma unroll
        for (int i = 0; i < 8; i++)
#pragma unroll
            for (int j = 0; j < 4; j++) sacc[i][j] = 0.f;
#pragma unroll
        for (int kb = 0; kb < 16; kb++) {
            uint2 aA = *(const uint2*)&Qs[(rb0 + g) * QS_STRIDE + kb * 8 + 2 * tig];
            uint2 aB = *(const uint2*)&Qs[(rb0 + g + 8) * QS_STRIDE + kb * 8 + 2 * tig];
#pragma unroll
            for (int ni = 0; ni < 8; ni++) {
                uint2 bb = *(const uint2*)&Ks[(ni * 8 + g) * KS_STRIDE + kb * 8 + 2 * tig];
                mma8(sacc[ni], aA.x, aB.x, aA.y, aB.y, bb.x, bb.y);
            }
        }
        // causal mask (only the last two kv blocks intersect the diagonal)
        if (kt >= 2 * qb) {
#pragma unroll
            for (int ni = 0; ni < 8; ni++)
#pragma unroll
                for (int j = 0; j < 4; j++) {
                    int col = k0 + ni * 8 + 2 * tig + (j & 1);
                    int row = q0 + rb0 + g + ((j >> 1) << 3);
                    if (col > row) sacc[ni][j] = -1e30f;
                }
        }
        // online softmax (rows rb0+g, rb0+g+8; each row shared by 4 lanes)
#pragma unroll
        for (int rr = 0; rr < 2; rr++) {
            float mx = -1e30f;
#pragma unroll
            for (int ni = 0; ni < 8; ni++)
                mx = fmaxf(mx, fmaxf(sacc[ni][rr * 2], sacc[ni][rr * 2 + 1]));
            mx = fmaxf(mx, __shfl_xor_sync(0xffffffffu, mx, 1));
            mx = fmaxf(mx, __shfl_xor_sync(0xffffffffu, mx, 2));
            float mnew = fmaxf(mrow[rr], mx);
            float corr = __expf(mrow[rr] - mnew);
            float rs = 0.f;
#pragma unroll
            for (int ni = 0; ni < 8; ni++) {
                float p0 = __expf(sacc[ni][rr * 2] - mnew);
                float p1 = __expf(sacc[ni][rr * 2 + 1] - mnew);
                sacc[ni][rr * 2] = p0;
                sacc[ni][rr * 2 + 1] = p1;
                rs += p0 + p1;
            }
            rs += __shfl_xor_sync(0xffffffffu, rs, 1);
            rs += __shfl_xor_sync(0xffffffffu, rs, 2);
            lrow[rr] = lrow[rr] * corr + rs;
            mrow[rr] = mnew;
#pragma unroll
            for (int ni = 0; ni < 16; ni++) {
                O[ni][rr * 2] *= corr;
                O[ni][rr * 2 + 1] *= corr;
            }
            int prow = rb0 + g + rr * 8;
#pragma unroll
            for (int ni = 0; ni < 8; ni++) {
                int c0 = ni * 8 + 2 * tig;
                Ps[prow * PS_STRIDE + ((c0 & ~7) | P8f(c0 & 7))] = f2tf(sacc[ni][rr * 2]);
                Ps[prow * PS_STRIDE + (((c0 + 1) & ~7) | P8f((c0 + 1) & 7))] =
                    f2tf(sacc[ni][rr * 2 + 1]);
            }
        }
        __syncwarp();
        // O += P @ V  (k = 64 kv, 16 n8-tiles over d)
#pragma unroll
        for (int kb = 0; kb < 8; kb++) {
            uint2 aA = *(const uint2*)&Ps[(rb0 + g) * PS_STRIDE + kb * 8 + 2 * tig];
            uint2 aB = *(const uint2*)&Ps[(rb0 + g + 8) * PS_STRIDE + kb * 8 + 2 * tig];
#pragma unroll
            for (int ni = 0; ni < 16; ni++) {
                uint2 bb = *(const uint2*)&Vs[(ni * 8 + g) * VS_STRIDE + kb * 8 + 2 * tig];
                mma8(O[ni], aA.x, aB.x, aA.y, aB.y, bb.x, bb.y);
            }
        }
    }

    // epilogue
    float* Ob = g_attn + ((size_t)(b * NQ + h)) * SEQ * HD;
#pragma unroll
    for (int rr = 0; rr < 2; rr++) {
        float inv = 1.f / lrow[rr];
        int r = q0 + rb0 + g + rr * 8;
#pragma unroll
        for (int ni = 0; ni < 16; ni++) {
            *(float2*)&Ob[(size_t)r * HD + ni * 8 + 2 * tig] =
                make_float2(O[ni][rr * 2] * inv, O[ni][rr * 2 + 1] * inv);
        }
    }
}

// ---------------- launch ------------------------------------------------------
extern "C" void kernel_launch(void* const* d_in, const int* in_sizes, int n_in,
                              void* d_out, int out_size) {
    const float* x  = (const float*)d_in[0];
    const float* Wq = (const float*)d_in[1];
    const float* Wk = (const float*)d_in[2];
    const float* Wv = (const float*)d_in[3];
    const float* Wo = (const float*)d_in[4];
    const float* qA = (const float*)d_in[5];
    const float* qB = (const float*)d_in[6];
    const float* kA = (const float*)d_in[7];
    const float* kB = (const float*)d_in[8];
    const float* vA = (const float*)d_in[9];
    const float* vB = (const float*)d_in[10];
    const float* oA = (const float*)d_in[11];
    const float* oB = (const float*)d_in[12];
    float* out = (float*)d_out;

    cudaFuncSetAttribute(gemm_kernel<0, NQ>, cudaFuncAttributeMaxDynamicSharedMemorySize, GEMM_SMEM);
    cudaFuncSetAttribute(gemm_kernel<1, NKV>, cudaFuncAttributeMaxDynamicSharedMemorySize, GEMM_SMEM);
    cudaFuncSetAttribute(gemm_kernel<2, NKV>, cudaFuncAttributeMaxDynamicSharedMemorySize, GEMM_SMEM);
    cudaFuncSetAttribute(gemm_kernel<3, NQ>, cudaFuncAttributeMaxDynamicSharedMemorySize, GEMM_SMEM);
    cudaFuncSetAttribute(flash_kernel, cudaFuncAttributeMaxDynamicSharedMemorySize, FLASH_SMEM);

    rope_table_kernel<<<512, 256>>>();
    lora_down_qkv_kernel<<<MROWS, 256>>>(x, qA, kA, vA);

    gemm_kernel<0, NQ><<<dim3(16, 32), 256, GEMM_SMEM>>>(x, Wq, qB, nullptr);
    gemm_kernel<1, NKV><<<dim3(8, 32), 256, GEMM_SMEM>>>(x, Wk, kB, nullptr);
    gemm_kernel<2, NKV><<<dim3(8, 32), 256, GEMM_SMEM>>>(x, Wv, vB, nullptr);

    flash_kernel<<<dim3(SEQ / 128, BATCH * NQ), 256, FLASH_SMEM>>>();

    lora_down_o_kernel<<<MROWS, 256>>>(oA);
    gemm_kernel<3, NQ><<<dim3(16, 32), 256, GEMM_SMEM>>>(x, Wo, oB, out);
}

// round 3
// speedup vs baseline: 2.9455x; 1.2923x over previous
#include <cuda_runtime.h>
#include <math.h>
#include <stdint.h>

#define HIDDEN 2048
#define NQ 16
#define NKV 8
#define HD 128
#define SEQ 2048
#define BATCH 2
#define MROWS 4096
#define RANK 8
#define LORA_SC 2.0f
#define SM_SCALE 0.08838834764831845f

// ---------------- scratch -----------------------------------------------------
__device__ float g_q[8388608];      // [B][NQ][S][D]
__device__ float g_k[4194304];      // [B][NKV][S][D]
__device__ float g_vT[4194304];     // [B][NKV][D][S]  (transposed V)
__device__ float g_attn[8388608];   // [B][NQ][S][D]
__device__ float g_tq[MROWS * RANK];
__device__ float g_tk[MROWS * RANK];
__device__ float g_tv[MROWS * RANK];
__device__ float g_to[MROWS * RANK];
__device__ float g_cos[SEQ * 64];
__device__ float g_sin[SEQ * 64];

// ---------------- helpers -----------------------------------------------------
__device__ __forceinline__ uint32_t f2tf(float x) {
    uint32_t r;
    asm("cvt.rna.tf32.f32 %0, %1;" : "=r"(r) : "f"(x));
    return r;
}

__device__ __forceinline__ void mma8(float* c, uint32_t a0, uint32_t a1,
                                     uint32_t a2, uint32_t a3,
                                     uint32_t b0, uint32_t b1) {
    asm volatile(
        "mma.sync.aligned.m16n8k8.row.col.f32.tf32.tf32.f32 "
        "{%0,%1,%2,%3}, {%4,%5,%6,%7}, {%8,%9}, {%0,%1,%2,%3};\n"
        : "+f"(c[0]), "+f"(c[1]), "+f"(c[2]), "+f"(c[3])
        : "r"(a0), "r"(a1), "r"(a2), "r"(a3), "r"(b0), "r"(b1));
}

__device__ __forceinline__ int mswz(int r) { return (r & 3) ^ ((r >> 2) & 3); }

// pack a float4 (k = c4..c4+3) into the fragment layout:
// word(k) = chunkbase + ((k&3)^m(r))*4 + ((k>>2)&3)
__device__ __forceinline__ void stFrag16(uint32_t* T, int r, int c4, float4 v) {
    int m = mswz(r);
    uint32_t* p = T + r * 16 + (c4 >> 2);
    p[(0 ^ m) << 2] = f2tf(v.x);
    p[(1 ^ m) << 2] = f2tf(v.y);
    p[(2 ^ m) << 2] = f2tf(v.z);
    p[(3 ^ m) << 2] = f2tf(v.w);
}

__device__ __forceinline__ void stFragS(uint32_t* T, int stride, int r, int c4,
                                        float4 v, float scale) {
    int m = mswz(r);
    uint32_t* p = T + r * stride + (c4 & ~15) + ((c4 >> 2) & 3);
    p[(0 ^ m) << 2] = f2tf(v.x * scale);
    p[(1 ^ m) << 2] = f2tf(v.y * scale);
    p[(2 ^ m) << 2] = f2tf(v.z * scale);
    p[(3 ^ m) << 2] = f2tf(v.w * scale);
}

// ---------------- RoPE tables -------------------------------------------------
__global__ void rope_table_kernel() {
    int idx = blockIdx.x * blockDim.x + threadIdx.x;
    if (idx >= SEQ * 64) return;
    int s = idx >> 6, f = idx & 63;
    double inv = pow(10000.0, -(double)(2 * f) / 128.0);
    double ang = (double)s * inv;
    g_cos[idx] = (float)cos(ang);
    g_sin[idx] = (float)sin(ang);
}

// ---------------- LoRA down-projections --------------------------------------
__global__ void lora_down_qkv_kernel(const float* __restrict__ x,
                                     const float* __restrict__ qA,
                                     const float* __restrict__ kA,
                                     const float* __restrict__ vA) {
    int m = blockIdx.x, tid = threadIdx.x;
    __shared__ float xs[HIDDEN];
    __shared__ float red[8][24];
    const float4* xr4 = (const float4*)(x + (size_t)m * HIDDEN);
    float4* xs4 = (float4*)xs;
    for (int i = tid; i < HIDDEN / 4; i += 256) xs4[i] = xr4[i];
    __syncthreads();
    float part[24];
#pragma unroll
    for (int j = 0; j < 24; j++) part[j] = 0.f;
    for (int h = tid; h < HIDDEN; h += 256) {
        float xv = xs[h];
#pragma unroll
        for (int r = 0; r < 8; r++) part[r]      += xv * qA[r * HIDDEN + h];
#pragma unroll
        for (int r = 0; r < 8; r++) part[8 + r]  += xv * kA[r * HIDDEN + h];
#pragma unroll
        for (int r = 0; r < 8; r++) part[16 + r] += xv * vA[r * HIDDEN + h];
    }
    int lane = tid & 31, w = tid >> 5;
#pragma unroll
    for (int j = 0; j < 24; j++) {
        float v = part[j];
#pragma unroll
        for (int o = 16; o > 0; o >>= 1) v += __shfl_xor_sync(0xffffffffu, v, o);
        if (lane == 0) red[w][j] = v;
    }
    __syncthreads();
    if (tid < 24) {
        float v = 0.f;
#pragma unroll
        for (int w2 = 0; w2 < 8; w2++) v += red[w2][tid];
        int r = tid & 7;
        if (tid < 8)       g_tq[m * RANK + r] = v;
        else if (tid < 16) g_tk[m * RANK + r] = v;
        else               g_tv[m * RANK + r] = v;
    }
}

__global__ void lora_down_o_kernel(const float* __restrict__ oA) {
    int m = blockIdx.x, tid = threadIdx.x;
    int b = m >> 11, s = m & (SEQ - 1);
    __shared__ float xs[NQ * HD];
    __shared__ float red[8][8];
    for (int f4 = tid; f4 < NQ * HD / 4; f4 += 256) {
        int k0 = f4 * 4;
        int h = k0 >> 7, d = k0 & 127;
        *(float4*)&xs[k0] =
            *(const float4*)&g_attn[(((size_t)(b * NQ + h)) * SEQ + s) * HD + d];
    }
    __syncthreads();
    float part[8];
#pragma unroll
    for (int r = 0; r < 8; r++) part[r] = 0.f;
    for (int k = tid; k < NQ * HD; k += 256) {
        float xv = xs[k];
#pragma unroll
        for (int r = 0; r < 8; r++) part[r] += xv * oA[r * (NQ * HD) + k];
    }
    int lane = tid & 31, w = tid >> 5;
#pragma unroll
    for (int r = 0; r < 8; r++) {
        float v = part[r];
#pragma unroll
        for (int o = 16; o > 0; o >>= 1) v += __shfl_xor_sync(0xffffffffu, v, o);
        if (lane == 0) red[w][r] = v;
    }
    __syncthreads();
    if (tid < 8) {
        float v = 0.f;
#pragma unroll
        for (int w2 = 0; w2 < 8; w2++) v += red[w2][tid];
        g_to[m * RANK + tid] = v;
    }
}

// ---------------- fused tf32 GEMM --------------------------------------------
// IS_O=0: fused QKV (n-blocks: 0-15 Q, 16-23 K, 24-31 V), A = x
// IS_O=1: O projection, A gathered from g_attn, writes Out
#define GEMM_SMEM (4 * 2048 * 4)

template <int IS_O>
__device__ __forceinline__ float4 ldAg(const float* __restrict__ x, int m, int kf) {
    if (IS_O) {
        int b = m >> 11, s = m & 2047, h = kf >> 7, d = kf & 127;
        return *(const float4*)&g_attn[(((size_t)(b * NQ + h)) * SEQ + s) * HD + d];
    }
    return *(const float4*)&x[(size_t)m * HIDDEN + kf];
}

template <int IS_O>
__global__ void __launch_bounds__(256) gemm2_kernel(
    const float* __restrict__ x,
    const float* __restrict__ Wqp, const float* __restrict__ Wkp,
    const float* __restrict__ Wvp,
    const float* __restrict__ qBp, const float* __restrict__ kBp,
    const float* __restrict__ vBp,
    float* __restrict__ Out) {
    extern __shared__ uint32_t sm[];
    uint32_t* As = sm;              // [2][2048]
    uint32_t* Bs = sm + 4096;       // [2][2048]
    const int tid = threadIdx.x, lane = tid & 31, wid = tid >> 5;
    const int wm = (wid & 3) * 32, wn = (wid >> 2) * 64;
    const int g = lane >> 2, tig = lane & 3;
    const int m0 = blockIdx.y * 128;
    const int nb = blockIdx.x;

    const float *W, *U, *T;
    int which, nrel0;
    if (IS_O) {
        which = 3; nrel0 = nb * 128;
        W = Wqp + (size_t)nrel0 * HIDDEN;   // Wo
        U = qBp + nrel0 * RANK;             // oB
        T = g_to;
    } else if (nb < 16) {
        which = 0; nrel0 = nb * 128;
        W = Wqp + (size_t)nrel0 * HIDDEN; U = qBp + nrel0 * RANK; T = g_tq;
    } else if (nb < 24) {
        which = 1; nrel0 = nb * 128 - 2048;
        W = Wkp + (size_t)nrel0 * HIDDEN; U = kBp + nrel0 * RANK; T = g_tk;
    } else {
        which = 2; nrel0 = nb * 128 - 3072;
        W = Wvp + (size_t)nrel0 * HIDDEN; U = vBp + nrel0 * RANK; T = g_tv;
    }

    const int m0l = (g & 3) ^ (g >> 2);
    const int ca = (tig ^ m0l) << 2;
    const int cb = (tig ^ m0l ^ 2) << 2;

    float acc0[8][4], acc1[8][4];
#pragma unroll
    for (int i = 0; i < 8; i++)
#pragma unroll
        for (int j = 0; j < 4; j++) { acc0[i][j] = 0.f; acc1[i][j] = 0.f; }

    const int row_ = tid >> 2, c4_ = (tid & 3) * 4;
    float4 ra0, ra1, rb0_, rb1_;

    ra0 = ldAg<IS_O>(x, m0 + row_, c4_);
    ra1 = ldAg<IS_O>(x, m0 + row_ + 64, c4_);
    rb0_ = *(const float4*)&W[(size_t)row_ * HIDDEN + c4_];
    rb1_ = *(const float4*)&W[(size_t)(row_ + 64) * HIDDEN + c4_];
    stFrag16(As, row_, c4_, ra0);
    stFrag16(As, row_ + 64, c4_, ra1);
    stFrag16(Bs, row_, c4_, rb0_);
    stFrag16(Bs, row_ + 64, c4_, rb1_);
    __syncthreads();

    const int NKC = HIDDEN / 16;
    for (int kc = 0; kc < NKC; kc++) {
        const uint32_t* Ab = As + (kc & 1) * 2048;
        const uint32_t* Bb = Bs + (kc & 1) * 2048;
        if (kc + 1 < NKC) {
            int kf = (kc + 1) * 16 + c4_;
            ra0 = ldAg<IS_O>(x, m0 + row_, kf);
            ra1 = ldAg<IS_O>(x, m0 + row_ + 64, kf);
            rb0_ = *(const float4*)&W[(size_t)row_ * HIDDEN + kf];
            rb1_ = *(const float4*)&W[(size_t)(row_ + 64) * HIDDEN + kf];
        }
        uint4 A0 = *(const uint4*)&Ab[(wm + g) * 16 + ca];
        uint4 A1 = *(const uint4*)&Ab[(wm + 8 + g) * 16 + cb];
        uint4 A2 = *(const uint4*)&Ab[(wm + 16 + g) * 16 + ca];
        uint4 A3 = *(const uint4*)&Ab[(wm + 24 + g) * 16 + cb];
#pragma unroll
        for (int ni = 0; ni < 8; ni++) {
            uint4 Bf = *(const uint4*)&Bb[(wn + ni * 8 + g) * 16 + ((ni & 1) ? cb : ca)];
            mma8(acc0[ni], A0.x, A1.x, A0.y, A1.y, Bf.x, Bf.y);
            mma8(acc0[ni], A0.z, A1.z, A0.w, A1.w, Bf.z, Bf.w);
            mma8(acc1[ni], A2.x, A3.x, A2.y, A3.y, Bf.x, Bf.y);
            mma8(acc1[ni], A2.z, A3.z, A2.w, A3.w, Bf.z, Bf.w);
        }
        __syncthreads();
        if (kc + 1 < NKC) {
            uint32_t* An = As + ((kc + 1) & 1) * 2048;
            uint32_t* Bn = Bs + ((kc + 1) & 1) * 2048;
            stFrag16(An, row_, c4_, ra0);
            stFrag16(An, row_ + 64, c4_, ra1);
            stFrag16(Bn, row_, c4_, rb0_);
            stFrag16(Bn, row_ + 64, c4_, rb1_);
        }
        __syncthreads();
    }

    // LoRA rank-8 tail (k8, fragments in kb0 slots of buffer 0)
    {
        int row = tid >> 1, c4 = (tid & 1) * 4;
        int m = mswz(row);
        float4 tv = *(const float4*)&T[(size_t)(m0 + row) * RANK + c4];
        uint32_t* p = As + row * 16 + (tid & 1);
        p[(0 ^ m) << 2] = f2tf(tv.x);
        p[(1 ^ m) << 2] = f2tf(tv.y);
        p[(2 ^ m) << 2] = f2tf(tv.z);
        p[(3 ^ m) << 2] = f2tf(tv.w);
        float4 uv = *(const float4*)&U[row * RANK + c4];
        uint32_t* q = Bs + row * 16 + (tid & 1);
        q[(0 ^ m) << 2] = f2tf(uv.x * LORA_SC);
        q[(1 ^ m) << 2] = f2tf(uv.y * LORA_SC);
        q[(2 ^ m) << 2] = f2tf(uv.z * LORA_SC);
        q[(3 ^ m) << 2] = f2tf(uv.w * LORA_SC);
    }
    __syncthreads();
    {
        uint2 tA0 = *(const uint2*)&As[(wm + g) * 16 + ca];
        uint2 tA1 = *(const uint2*)&As[(wm + 8 + g) * 16 + cb];
        uint2 tA2 = *(const uint2*)&As[(wm + 16 + g) * 16 + ca];
        uint2 tA3 = *(const uint2*)&As[(wm + 24 + g) * 16 + cb];
#pragma unroll
        for (int ni = 0; ni < 8; ni++) {
            uint2 tB = *(const uint2*)&Bs[(wn + ni * 8 + g) * 16 + ((ni & 1) ? cb : ca)];
            mma8(acc0[ni], tA0.x, tA1.x, tA0.y, tA1.y, tB.x, tB.y);
            mma8(acc1[ni], tA2.x, tA3.x, tA2.y, tA3.y, tB.x, tB.y);
        }
    }

    // epilogue
#pragma unroll
    for (int mi = 0; mi < 2; mi++) {
#pragma unroll
        for (int rr = 0; rr < 2; rr++) {
            int m = m0 + wm + mi * 16 + g + rr * 8;
            int s = m & 2047, b = m >> 11;
#pragma unroll
            for (int ni = 0; ni < 8; ni++) {
                int nrel = nrel0 + wn + ni * 8 + 2 * tig;
                float v0 = (mi ? acc1 : acc0)[ni][rr * 2 + 0];
                float v1 = (mi ? acc1 : acc0)[ni][rr * 2 + 1];
                int d = nrel & 127;
                if (which <= 1) {
                    int f = d >> 1;
                    float c = g_cos[s * 64 + f], sn = g_sin[s * 64 + f];
                    float t0 = v0 * c - v1 * sn;
                    v1 = v0 * sn + v1 * c;
                    v0 = t0;
                }
                if (which == 3) {
                    *(float2*)&Out[(size_t)m * HIDDEN + nrel] = make_float2(v0, v1);
                } else if (which == 0) {
                    *(float2*)&g_q[(((size_t)(b * NQ + (nrel >> 7))) * SEQ + s) * HD + d] =
                        make_float2(v0, v1);
                } else if (which == 1) {
                    *(float2*)&g_k[(((size_t)(b * NKV + (nrel >> 7))) * SEQ + s) * HD + d] =
                        make_float2(v0, v1);
                } else {
                    float* p = g_vT + (((size_t)(b * NKV + (nrel >> 7))) * HD + d) * SEQ + s;
                    p[0] = v0;
                    p[SEQ] = v1;
                }
            }
        }
    }
}

// ---------------- tensor-core causal flash attention --------------------------
#define QS_ST 144
#define KS_ST 144
#define VS_ST 80
#define PS_ST 80
#define FLASH_SMEM ((128 * QS_ST + 64 * KS_ST + 128 * VS_ST + 128 * PS_ST) * 4)

__global__ void __launch_bounds__(256) flash_kernel() {
    extern __shared__ uint32_t sm[];
    uint32_t* Qs = sm;                    // [128][144]
    uint32_t* Ks = Qs + 128 * QS_ST;      // [64][144]
    uint32_t* Vs = Ks + 64 * KS_ST;       // [128(d)][80] (kv packed)
    uint32_t* Ps = Vs + 128 * VS_ST;      // [128][80]
    int tid = threadIdx.x, lane = tid & 31, wid = tid >> 5;
    int g = lane >> 2, tig = lane & 3;
    int qb = blockIdx.x, bh = blockIdx.y;
    int b = bh >> 4, h = bh & 15, kvh = h >> 1;
    const float* Qb = g_q + ((size_t)(b * NQ + h)) * SEQ * HD;
    const float* Kb = g_k + ((size_t)(b * NKV + kvh)) * SEQ * HD;
    const float* Vb = g_vT + ((size_t)(b * NKV + kvh)) * HD * SEQ;
    int q0 = qb * 128;
    int rb0 = wid * 16;

    const int m0l = (g & 3) ^ (g >> 2);
    const int ca = (tig ^ m0l) << 2;
    const int cb = (tig ^ m0l ^ 2) << 2;

    for (int f = tid; f < 128 * 32; f += 256) {
        int r = f >> 5, c4 = (f & 31) << 2;
        float4 v = *(const float4*)&Qb[(size_t)(q0 + r) * HD + c4];
        stFragS(Qs, QS_ST, r, c4, v, SM_SCALE);
    }

    float O[16][4];
#pragma unroll
    for (int i = 0; i < 16; i++)
#pragma unroll
        for (int j = 0; j < 4; j++) O[i][j] = 0.f;
    float mrow[2] = {-1e30f, -1e30f}, lrow[2] = {0.f, 0.f};

    int ktmax = 2 * qb + 1;
    for (int kt = 0; kt <= ktmax; kt++) {
        __syncthreads();
        int k0 = kt * 64;
        for (int f = tid; f < 64 * 32; f += 256) {
            int r = f >> 5, c4 = (f & 31) << 2;
            float4 kv = *(const float4*)&Kb[(size_t)(k0 + r) * HD + c4];
            stFragS(Ks, KS_ST, r, c4, kv, 1.f);
        }
        for (int f = tid; f < 128 * 16; f += 256) {
            int d = f >> 4, c4 = (f & 15) << 2;
            float4 vv = *(const float4*)&Vb[(size_t)d * SEQ + k0 + c4];
            stFragS(Vs, VS_ST, d, c4, vv, 1.f);
        }
        __syncthreads();

        float sacc[8][4];
#pragma unroll
        for (int i = 0; i < 8; i++)
#pragma unroll
            for (int j = 0; j < 4; j++) sacc[i][j] = 0.f;
#pragma unroll
        for (int kb = 0; kb < 8; kb++) {
            int off = kb * 16;
            uint4 qa = *(const uint4*)&Qs[(rb0 + g) * QS_ST + off + ca];
            uint4 qz = *(const uint4*)&Qs[(rb0 + 8 + g) * QS_ST + off + cb];
#pragma unroll
            for (int ni = 0; ni < 8; ni++) {
                uint4 kf = *(const uint4*)&Ks[(ni * 8 + g) * KS_ST + off + ((ni & 1) ? cb : ca)];
                mma8(sacc[ni], qa.x, qz.x, qa.y, qz.y, kf.x, kf.y);
                mma8(sacc[ni], qa.z, qz.z, qa.w, qz.w, kf.z, kf.w);
            }
        }
        if (kt >= 2 * qb) {
#pragma unroll
            for (int ni = 0; ni < 8; ni++)
#pragma unroll
                for (int j = 0; j < 4; j++) {
                    int col = k0 + ni * 8 + 2 * tig + (j & 1);
                    int row = q0 + rb0 + g + ((j >> 1) << 3);
                    if (col > row) sacc[ni][j] = -1e30f;
                }
        }
#pragma unroll
        for (int rr = 0; rr < 2; rr++) {
            float mx = -1e30f;
#pragma unroll
            for (int ni = 0; ni < 8; ni++)
                mx = fmaxf(mx, fmaxf(sacc[ni][rr * 2], sacc[ni][rr * 2 + 1]));
            mx = fmaxf(mx, __shfl_xor_sync(0xffffffffu, mx, 1));
            mx = fmaxf(mx, __shfl_xor_sync(0xffffffffu, mx, 2));
            float mnew = fmaxf(mrow[rr], mx);
            float corr = __expf(mrow[rr] - mnew);
            float rs = 0.f;
#pragma unroll
            for (int ni = 0; ni < 8; ni++) {
                float p0 = __expf(sacc[ni][rr * 2] - mnew);
                float p1 = __expf(sacc[ni][rr * 2 + 1] - mnew);
                sacc[ni][rr * 2] = p0;
                sacc[ni][rr * 2 + 1] = p1;
                rs += p0 + p1;
            }
            rs += __shfl_xor_sync(0xffffffffu, rs, 1);
            rs += __shfl_xor_sync(0xffffffffu, rs, 2);
            lrow[rr] = lrow[rr] * corr + rs;
            mrow[rr] = mnew;
#pragma unroll
            for (int ni = 0; ni < 16; ni++) {
                O[ni][rr * 2] *= corr;
                O[ni][rr * 2 + 1] *= corr;
            }
            int prow = rb0 + g + rr * 8;
            int mp = m0l ^ (rr ? 2 : 0);
            uint32_t* Pr = Ps + prow * PS_ST;
            int e0 = (2 * tig) & 3, e1 = (2 * tig + 1) & 3;
#pragma unroll
            for (int ni = 0; ni < 8; ni++) {
                int base = (ni >> 1) * 16 + ((ni & 1) * 2 + (tig >> 1));
                Pr[base + ((e0 ^ mp) << 2)] = f2tf(sacc[ni][rr * 2]);
                Pr[base + ((e1 ^ mp) << 2)] = f2tf(sacc[ni][rr * 2 + 1]);
            }
        }
        __syncwarp();
#pragma unroll
        for (int kb = 0; kb < 4; kb++) {
            int off = kb * 16;
            uint4 pa = *(const uint4*)&Ps[(rb0 + g) * PS_ST + off + ca];
            uint4 pz = *(const uint4*)&Ps[(rb0 + 8 + g) * PS_ST + off + cb];
#pragma unroll
            for (int ni = 0; ni < 16; ni++) {
                uint4 vf = *(const uint4*)&Vs[(ni * 8 + g) * VS_ST + off + ((ni & 1) ? cb : ca)];
                mma8(O[ni], pa.x, pz.x, pa.y, pz.y, vf.x, vf.y);
                mma8(O[ni], pa.z, pz.z, pa.w, pz.w, vf.z, vf.w);
            }
        }
    }

    float* Ob = g_attn + ((size_t)(b * NQ + h)) * SEQ * HD;
#pragma unroll
    for (int rr = 0; rr < 2; rr++) {
        float inv = 1.f / lrow[rr];
        int r = q0 + rb0 + g + rr * 8;
#pragma unroll
        for (int ni = 0; ni < 16; ni++) {
            *(float2*)&Ob[(size_t)r * HD + ni * 8 + 2 * tig] =
                make_float2(O[ni][rr * 2] * inv, O[ni][rr * 2 + 1] * inv);
        }
    }
}

// ---------------- launch ------------------------------------------------------
extern "C" void kernel_launch(void* const* d_in, const int* in_sizes, int n_in,
                              void* d_out, int out_size) {
    const float* x  = (const float*)d_in[0];
    const float* Wq = (const float*)d_in[1];
    const float* Wk = (const float*)d_in[2];
    const float* Wv = (const float*)d_in[3];
    const float* Wo = (const float*)d_in[4];
    const float* qA = (const float*)d_in[5];
    const float* qB = (const float*)d_in[6];
    const float* kA = (const float*)d_in[7];
    const float* kB = (const float*)d_in[8];
    const float* vA = (const float*)d_in[9];
    const float* vB = (const float*)d_in[10];
    const float* oA = (const float*)d_in[11];
    const float* oB = (const float*)d_in[12];
    float* out = (float*)d_out;

    cudaFuncSetAttribute(gemm2_kernel<0>, cudaFuncAttributeMaxDynamicSharedMemorySize, GEMM_SMEM);
    cudaFuncSetAttribute(gemm2_kernel<1>, cudaFuncAttributeMaxDynamicSharedMemorySize, GEMM_SMEM);
    cudaFuncSetAttribute(flash_kernel, cudaFuncAttributeMaxDynamicSharedMemorySize, FLASH_SMEM);

    rope_table_kernel<<<512, 256>>>();
    lora_down_qkv_kernel<<<MROWS, 256>>>(x, qA, kA, vA);

    gemm2_kernel<0><<<dim3(32, 32), 256, GEMM_SMEM>>>(x, Wq, Wk, Wv, qB, kB, vB, nullptr);

    flash_kernel<<<dim3(SEQ / 128, BATCH * NQ), 256, FLASH_SMEM>>>();

    lora_down_o_kernel<<<MROWS, 256>>>(oA);
    gemm2_kernel<1><<<dim3(16, 32), 256, GEMM_SMEM>>>(x, Wo, nullptr, nullptr, oB, nullptr, nullptr, out);
}

// round 4
// speedup vs baseline: 4.1474x; 1.4081x over previous
#include <cuda_runtime.h>
#include <math.h>
#include <stdint.h>

#define HIDDEN 2048
#define NQ 16
#define NKV 8
#define HD 128
#define SEQ 2048
#define BATCH 2
#define MROWS 4096
#define RANK 8
#define LORA_SC 2.0f
#define SM_SCALE 0.08838834764831845f

// ---------------- scratch -----------------------------------------------------
__device__ float g_q[8388608];      // [B][NQ][S][D]   (tf32-rounded, pre-scaled)
__device__ float g_k[4194304];      // [B][NKV][S][D]  (tf32-rounded)
__device__ float g_vT[4194304];     // [B][NKV][D][S]  (tf32-rounded, transposed)
__device__ float g_attn[8388608];   // [B][NQ][S][D]   (tf32-rounded)
__device__ float g_xr[8388608];     // tf32-rounded x
__device__ float g_wq[4194304];
__device__ float g_wk[2097152];
__device__ float g_wv[2097152];
__device__ float g_wo[4194304];
__device__ float g_tq[MROWS * RANK];
__device__ float g_tk[MROWS * RANK];
__device__ float g_tv[MROWS * RANK];
__device__ float g_to[MROWS * RANK];
__device__ float g_cos[SEQ * 64];
__device__ float g_sin[SEQ * 64];

// ---------------- helpers -----------------------------------------------------
__device__ __forceinline__ uint32_t f2tf(float x) {
    uint32_t r;
    asm("cvt.rna.tf32.f32 %0, %1;" : "=r"(r) : "f"(x));
    return r;
}

__device__ __forceinline__ void mma8(float* c, uint32_t a0, uint32_t a1,
                                     uint32_t a2, uint32_t a3,
                                     uint32_t b0, uint32_t b1) {
    asm volatile(
        "mma.sync.aligned.m16n8k8.row.col.f32.tf32.tf32.f32 "
        "{%0,%1,%2,%3}, {%4,%5,%6,%7}, {%8,%9}, {%0,%1,%2,%3};\n"
        : "+f"(c[0]), "+f"(c[1]), "+f"(c[2]), "+f"(c[3])
        : "r"(a0), "r"(a1), "r"(a2), "r"(a3), "r"(b0), "r"(b1));
}

__device__ __forceinline__ uint32_t s2u(const void* p) {
    uint32_t r;
    asm("{ .reg .u64 t; cvta.to.shared.u64 t, %1; cvt.u32.u64 %0, t; }"
        : "=r"(r) : "l"(p));
    return r;
}

#define CPA16(dst, src) \
    asm volatile("cp.async.cg.shared.global [%0], [%1], 16;\n" ::"r"(dst), "l"(src))
#define CPC() asm volatile("cp.async.commit_group;\n")
#define CPW(n) asm volatile("cp.async.wait_group %0;\n" ::"n"(n))

__device__ __forceinline__ void ldsm4(uint4& d, uint32_t a) {
    asm volatile("ldmatrix.sync.aligned.m8n8.x4.shared.b16 {%0,%1,%2,%3}, [%4];\n"
                 : "=r"(d.x), "=r"(d.y), "=r"(d.z), "=r"(d.w)
                 : "r"(a));
}

// ---------------- RoPE tables -------------------------------------------------
__global__ void rope_table_kernel() {
    int idx = blockIdx.x * blockDim.x + threadIdx.x;
    if (idx >= SEQ * 64) return;
    int s = idx >> 6, f = idx & 63;
    double inv = pow(10000.0, -(double)(2 * f) / 128.0);
    double ang = (double)s * inv;
    g_cos[idx] = (float)cos(ang);
    g_sin[idx] = (float)sin(ang);
}

// ---------------- pre-round inputs to tf32 ------------------------------------
// segments (float4 counts): x 2097152 | Wq 1048576 | Wk 524288 | Wv 524288 | Wo 1048576
__global__ void convert_all_kernel(const float* __restrict__ x,
                                   const float* __restrict__ Wq,
                                   const float* __restrict__ Wk,
                                   const float* __restrict__ Wv,
                                   const float* __restrict__ Wo) {
    int i = blockIdx.x * blockDim.x + threadIdx.x;
    const float4* src;
    float4* dst;
    int j;
    if (i < 2097152) { src = (const float4*)x; dst = (float4*)g_xr; j = i; }
    else if (i < 3145728) { src = (const float4*)Wq; dst = (float4*)g_wq; j = i - 2097152; }
    else if (i < 3670016) { src = (const float4*)Wk; dst = (float4*)g_wk; j = i - 3145728; }
    else if (i < 4194304) { src = (const float4*)Wv; dst = (float4*)g_wv; j = i - 3670016; }
    else if (i < 5242880) { src = (const float4*)Wo; dst = (float4*)g_wo; j = i - 4194304; }
    else return;
    float4 v = src[j];
    v.x = __uint_as_float(f2tf(v.x));
    v.y = __uint_as_float(f2tf(v.y));
    v.z = __uint_as_float(f2tf(v.z));
    v.w = __uint_as_float(f2tf(v.w));
    dst[j] = v;
}

// ---------------- LoRA down-projections --------------------------------------
__global__ void lora_down_qkv_kernel(const float* __restrict__ x,
                                     const float* __restrict__ qA,
                                     const float* __restrict__ kA,
                                     const float* __restrict__ vA) {
    int m = blockIdx.x, tid = threadIdx.x;
    __shared__ float xs[HIDDEN];
    __shared__ float red[8][24];
    const float4* xr4 = (const float4*)(x + (size_t)m * HIDDEN);
    float4* xs4 = (float4*)xs;
    for (int i = tid; i < HIDDEN / 4; i += 256) xs4[i] = xr4[i];
    __syncthreads();
    float part[24];
#pragma unroll
    for (int j = 0; j < 24; j++) part[j] = 0.f;
    for (int h = tid; h < HIDDEN; h += 256) {
        float xv = xs[h];
#pragma unroll
        for (int r = 0; r < 8; r++) part[r]      += xv * qA[r * HIDDEN + h];
#pragma unroll
        for (int r = 0; r < 8; r++) part[8 + r]  += xv * kA[r * HIDDEN + h];
#pragma unroll
        for (int r = 0; r < 8; r++) part[16 + r] += xv * vA[r * HIDDEN + h];
    }
    int lane = tid & 31, w = tid >> 5;
#pragma unroll
    for (int j = 0; j < 24; j++) {
        float v = part[j];
#pragma unroll
        for (int o = 16; o > 0; o >>= 1) v += __shfl_xor_sync(0xffffffffu, v, o);
        if (lane == 0) red[w][j] = v;
    }
    __syncthreads();
    if (tid < 24) {
        float v = 0.f;
#pragma unroll
        for (int w2 = 0; w2 < 8; w2++) v += red[w2][tid];
        int r = tid & 7;
        if (tid < 8)       g_tq[m * RANK + r] = v;
        else if (tid < 16) g_tk[m * RANK + r] = v;
        else               g_tv[m * RANK + r] = v;
    }
}

__global__ void lora_down_o_kernel(const float* __restrict__ oA) {
    int m = blockIdx.x, tid = threadIdx.x;
    int b = m >> 11, s = m & (SEQ - 1);
    __shared__ float xs[NQ * HD];
    __shared__ float red[8][8];
    for (int f4 = tid; f4 < NQ * HD / 4; f4 += 256) {
        int k0 = f4 * 4;
        int h = k0 >> 7, d = k0 & 127;
        *(float4*)&xs[k0] =
            *(const float4*)&g_attn[(((size_t)(b * NQ + h)) * SEQ + s) * HD + d];
    }
    __syncthreads();
    float part[8];
#pragma unroll
    for (int r = 0; r < 8; r++) part[r] = 0.f;
    for (int k = tid; k < NQ * HD; k += 256) {
        float xv = xs[k];
#pragma unroll
        for (int r = 0; r < 8; r++) part[r] += xv * oA[r * (NQ * HD) + k];
    }
    int lane = tid & 31, w = tid >> 5;
#pragma unroll
    for (int r = 0; r < 8; r++) {
        float v = part[r];
#pragma unroll
        for (int o = 16; o > 0; o >>= 1) v += __shfl_xor_sync(0xffffffffu, v, o);
        if (lane == 0) red[w][r] = v;
    }
    __syncthreads();
    if (tid < 8) {
        float v = 0.f;
#pragma unroll
        for (int w2 = 0; w2 < 8; w2++) v += red[w2][tid];
        g_to[m * RANK + tid] = v;
    }
}

// ---------------- cp.async + ldmatrix tf32 GEMM --------------------------------
// A[128][k] row-major, B rows = n (k-major). Granule (16B) swizzle for k16 chunks:
//   word(r, j granule, i) = r*16 + ((j ^ ((r>>1)&3))<<2) + i
#define GEMM_SMEM 65536

template <int IS_O>
__global__ void __launch_bounds__(256, 2) gemm3_kernel(
    const float* __restrict__ qBp, const float* __restrict__ kBp,
    const float* __restrict__ vBp, float* __restrict__ Out) {
    extern __shared__ uint32_t sm[];
    const int tid = threadIdx.x, lane = tid & 31, wid = tid >> 5;
    const int g = lane >> 2, tig = lane & 3;
    const int wm = (wid & 3) * 32, wn = (wid >> 2) * 64;
    const int m0 = blockIdx.y * 128;
    const int nb = blockIdx.x;

    const float *W, *U, *T;
    int which, nrel0;
    if (IS_O) {
        which = 3; nrel0 = nb * 128;
        W = g_wo + (size_t)nrel0 * HIDDEN; U = qBp + nrel0 * RANK; T = g_to;
    } else if (nb < 16) {
        which = 0; nrel0 = nb * 128;
        W = g_wq + (size_t)nrel0 * HIDDEN; U = qBp + nrel0 * RANK; T = g_tq;
    } else if (nb < 24) {
        which = 1; nrel0 = nb * 128 - 2048;
        W = g_wk + (size_t)nrel0 * HIDDEN; U = kBp + nrel0 * RANK; T = g_tk;
    } else {
        which = 2; nrel0 = nb * 128 - 3072;
        W = g_wv + (size_t)nrel0 * HIDDEN; U = vBp + nrel0 * RANK; T = g_tv;
    }

    const uint32_t smb = s2u(sm);

    // fill addressing (each thread: 2 A granules + 2 B granules per stage)
    const int fr = tid >> 1;
    const int fj0 = (tid & 1) * 2;
    const int fsw = (fr >> 1) & 3;
    const uint32_t dA0 = smb + (fr * 16) * 4;
    const uint32_t dB0 = smb + (8192 + fr * 16) * 4;
    const char* srcB = (const char*)W + (size_t)fr * HIDDEN * 4;
    size_t aoff;
    if (IS_O) {
        int m = m0 + fr, b = m >> 11, s = m & 2047;
        aoff = (((size_t)(b * NQ)) * SEQ + s) * HD;
    } else {
        aoff = (size_t)(m0 + fr) * HIDDEN;
    }

    auto fill = [&](int stage, int kc) {
        uint32_t sb = stage * 2048u * 4u;
#pragma unroll
        for (int u = 0; u < 2; u++) {
            int j = fj0 + u;
            int k = kc * 16 + j * 4;
            const char* sA;
            if (IS_O) {
                int hh = k >> 7, dd = k & 127;
                sA = (const char*)g_attn + (aoff + (size_t)hh * SEQ * HD + dd) * 4;
            } else {
                sA = (const char*)g_xr + (aoff + k) * 4;
            }
            uint32_t dsw = (uint32_t)((j ^ fsw) << 4);
            CPA16(dA0 + sb + dsw, sA);
            CPA16(dB0 + sb + dsw, srcB + (size_t)k * 4);
        }
    };

    // ldmatrix lane constants
    const int rowAoff = (lane & 7) + ((lane >> 3) & 1) * 8;
    const int hiA = lane >> 4;
    const int swA = (rowAoff >> 1) & 3;
    const int rowBoff = (lane & 7) + ((lane >> 4) << 3);
    const int hiB = (lane >> 3) & 1;
    const int swB = (rowBoff >> 1) & 3;
    uint32_t aAddr[2], bAddr[4];
#pragma unroll
    for (int mt = 0; mt < 2; mt++)
        aAddr[mt] = smb + ((wm + mt * 16 + rowAoff) * 16) * 4;
#pragma unroll
    for (int p = 0; p < 4; p++)
        bAddr[p] = smb + ((8192 + (wn + p * 16 + rowBoff) * 16)) * 4;

    float acc[2][8][4];
#pragma unroll
    for (int a = 0; a < 2; a++)
#pragma unroll
        for (int b2 = 0; b2 < 8; b2++)
#pragma unroll
            for (int c = 0; c < 4; c++) acc[a][b2][c] = 0.f;

    // pipeline
    for (int s = 0; s < 3; s++) { fill(s, s); CPC(); }

    const int NKC = HIDDEN / 16;
    for (int kc = 0; kc < NKC; kc++) {
        CPW(2);
        __syncthreads();
        if (kc + 3 < NKC) { fill((kc + 3) & 3, kc + 3); CPC(); } else { CPC(); }
        uint32_t sb = (kc & 3) * 2048u * 4u;
#pragma unroll
        for (int c = 0; c < 2; c++) {
            uint4 Af0, Af1;
            uint32_t ga = (uint32_t)((((2 * c + hiA) ^ swA) << 4));
            ldsm4(Af0, aAddr[0] + sb + ga);
            ldsm4(Af1, aAddr[1] + sb + ga);
            uint32_t gb = (uint32_t)((((2 * c + hiB) ^ swB) << 4));
#pragma unroll
            for (int p = 0; p < 4; p++) {
                uint4 Bf;
                ldsm4(Bf, bAddr[p] + sb + gb);
                mma8(acc[0][2 * p],     Af0.x, Af0.y, Af0.z, Af0.w, Bf.x, Bf.y);
                mma8(acc[0][2 * p + 1], Af0.x, Af0.y, Af0.z, Af0.w, Bf.z, Bf.w);
                mma8(acc[1][2 * p],     Af1.x, Af1.y, Af1.z, Af1.w, Bf.x, Bf.y);
                mma8(acc[1][2 * p + 1], Af1.x, Af1.y, Af1.z, Af1.w, Bf.z, Bf.w);
            }
        }
    }

    // LoRA rank-8 tail through stage 0, chunk 0 (granules 0,1)
    __syncthreads();
    {
        int r = tid >> 1, hf = tid & 1;
        int gsw = hf ^ ((r >> 1) & 3);
        float4 tv = *(const float4*)&T[(size_t)(m0 + r) * RANK + hf * 4];
        uint32_t* p = sm + r * 16 + (gsw << 2);
        p[0] = f2tf(tv.x); p[1] = f2tf(tv.y); p[2] = f2tf(tv.z); p[3] = f2tf(tv.w);
        float4 uv = *(const float4*)&U[r * RANK + hf * 4];
        uint32_t* q = sm + 8192 + r * 16 + (gsw << 2);
        q[0] = f2tf(uv.x * LORA_SC); q[1] = f2tf(uv.y * LORA_SC);
        q[2] = f2tf(uv.z * LORA_SC); q[3] = f2tf(uv.w * LORA_SC);
    }
    __syncthreads();
    {
        uint4 Af0, Af1;
        uint32_t ga = (uint32_t)(((hiA ^ swA) << 4));
        ldsm4(Af0, aAddr[0] + ga);
        ldsm4(Af1, aAddr[1] + ga);
        uint32_t gb = (uint32_t)(((hiB ^ swB) << 4));
#pragma unroll
        for (int p = 0; p < 4; p++) {
            uint4 Bf;
            ldsm4(Bf, bAddr[p] + gb);
            mma8(acc[0][2 * p],     Af0.x, Af0.y, Af0.z, Af0.w, Bf.x, Bf.y);
            mma8(acc[0][2 * p + 1], Af0.x, Af0.y, Af0.z, Af0.w, Bf.z, Bf.w);
            mma8(acc[1][2 * p],     Af1.x, Af1.y, Af1.z, Af1.w, Bf.x, Bf.y);
            mma8(acc[1][2 * p + 1], Af1.x, Af1.y, Af1.z, Af1.w, Bf.z, Bf.w);
        }
    }

    // epilogue
#pragma unroll
    for (int mt = 0; mt < 2; mt++) {
#pragma unroll
        for (int rr = 0; rr < 2; rr++) {
            int m = m0 + wm + mt * 16 + g + rr * 8;
            int s = m & 2047, b = m >> 11;
#pragma unroll
            for (int ni = 0; ni < 8; ni++) {
                int nrel = nrel0 + wn + ni * 8 + 2 * tig;
                float v0 = acc[mt][ni][rr * 2 + 0];
                float v1 = acc[mt][ni][rr * 2 + 1];
                int d = nrel & 127;
                if (which <= 1) {
                    int f = d >> 1;
                    float c = g_cos[s * 64 + f], sn = g_sin[s * 64 + f];
                    float t0 = v0 * c - v1 * sn;
                    v1 = v0 * sn + v1 * c;
                    v0 = t0;
                }
                if (which == 3) {
                    *(float2*)&Out[(size_t)m * HIDDEN + nrel] = make_float2(v0, v1);
                } else if (which == 0) {
                    float2 o = make_float2(__uint_as_float(f2tf(v0 * SM_SCALE)),
                                           __uint_as_float(f2tf(v1 * SM_SCALE)));
                    *(float2*)&g_q[(((size_t)(b * NQ + (nrel >> 7))) * SEQ + s) * HD + d] = o;
                } else if (which == 1) {
                    float2 o = make_float2(__uint_as_float(f2tf(v0)),
                                           __uint_as_float(f2tf(v1)));
                    *(float2*)&g_k[(((size_t)(b * NKV + (nrel >> 7))) * SEQ + s) * HD + d] = o;
                } else {
                    float* p = g_vT + (((size_t)(b * NKV + (nrel >> 7))) * HD + d) * SEQ + s;
                    p[0] = __uint_as_float(f2tf(v0));
                    p[SEQ] = __uint_as_float(f2tf(v1));
                }
            }
        }
    }
}

// ---------------- flash attention: cp.async + ldmatrix -------------------------
// smem words: Q [0,16384) | K0 [16384,24576) | K1 [24576,32768)
//             V0 [32768,40960) | V1 [40960,49152) | P [49152,57344)
// 128-word rows: word(r,j,i) = r*128 + ((j ^ (r&7))<<2) + i   (j<32)
//  64-word rows: word(r,j,i) = r*64  + ((j ^ (r&7))<<2) + i   (j<16)
#define FL_SMEM 229376

__global__ void __launch_bounds__(256) flash_kernel() {
    extern __shared__ uint32_t sm[];
    const int tid = threadIdx.x, lane = tid & 31, wid = tid >> 5;
    const int g = lane >> 2, tig = lane & 3;
    int qb = (gridDim.x - 1) - blockIdx.x;   // longest blocks first
    int bh = blockIdx.y;
    int b = bh >> 4, h = bh & 15, kvh = h >> 1;
    const float* Qb = g_q + ((size_t)(b * NQ + h)) * SEQ * HD;
    const float* Kb = g_k + ((size_t)(b * NKV + kvh)) * SEQ * HD;
    const float* Vb = g_vT + ((size_t)(b * NKV + kvh)) * HD * SEQ;
    int q0 = qb * 128, rb0 = wid * 16;
    const uint32_t smb = s2u(sm);

    // ldmatrix lane constants
    const int rowAoff = (lane & 7) + ((lane >> 3) & 1) * 8;
    const int hiA = lane >> 4;
    const int swA = rowAoff & 7;
    const int rowBoff = (lane & 7) + ((lane >> 4) << 3);
    const int hiB = (lane >> 3) & 1;
    const int swB = rowBoff & 7;

    const uint32_t qA_base = smb + ((rb0 + rowAoff) * 128) * 4;
    const uint32_t pA_base = smb + (49152 + (rb0 + rowAoff) * 64) * 4;
    uint32_t kB_base[4], vB_base[8];
#pragma unroll
    for (int p = 0; p < 4; p++)
        kB_base[p] = smb + (16384 + (p * 16 + rowBoff) * 128) * 4;
#pragma unroll
    for (int p = 0; p < 8; p++)
        vB_base[p] = smb + (32768 + (p * 16 + rowBoff) * 64) * 4;

    // Q fill (4096 granules)
    {
        const char* Qsrc = (const char*)(Qb + (size_t)q0 * HD);
#pragma unroll
        for (int i = 0; i < 16; i++) {
            int gid = i * 256 + tid;
            int r = gid >> 5, j = gid & 31;
            CPA16(smb + (r * 128 + ((j ^ (r & 7)) << 2)) * 4,
                  Qsrc + ((size_t)r * HD + j * 4) * 4);
        }
    }
    auto fillKV = [&](int kt, int st) {
        int k0 = kt * 64;
        uint32_t kst = smb + (16384 + st * 8192) * 4;
        uint32_t vst = smb + (32768 + st * 8192) * 4;
#pragma unroll
        for (int i = 0; i < 8; i++) {
            int gid = i * 256 + tid;
            int r = gid >> 5, j = gid & 31;
            CPA16(kst + (r * 128 + ((j ^ (r & 7)) << 2)) * 4,
                  (const char*)(Kb + (size_t)(k0 + r) * HD + j * 4));
            int rv = gid >> 4, jv = gid & 15;
            CPA16(vst + (rv * 64 + ((jv ^ (rv & 7)) << 2)) * 4,
                  (const char*)(Vb + (size_t)rv * SEQ + k0 + jv * 4));
        }
    };
    fillKV(0, 0);
    CPC();   // group 0 = Q + K0/V0

    float O[16][4];
#pragma unroll
    for (int i = 0; i < 16; i++)
#pragma unroll
        for (int j = 0; j < 4; j++) O[i][j] = 0.f;
    float mrow[2] = {-1e30f, -1e30f}, lrow[2] = {0.f, 0.f};

    int ktmax = 2 * qb + 1;
    for (int kt = 0; kt <= ktmax; kt++) {
        __syncthreads();   // all warps done with stage (kt-1)&1
        if (kt < ktmax) { fillKV(kt + 1, (kt + 1) & 1); CPC(); } else { CPC(); }
        CPW(1);
        __syncthreads();   // stage kt&1 ready and visible
        uint32_t ksb = (kt & 1) ? 8192u * 4u : 0u;
        int k0 = kt * 64;

        // S = Q K^T
        float sacc[8][4];
#pragma unroll
        for (int i = 0; i < 8; i++)
#pragma unroll
            for (int j = 0; j < 4; j++) sacc[i][j] = 0.f;
#pragma unroll
        for (int c = 0; c < 16; c++) {
            uint4 Qf;
            ldsm4(Qf, qA_base + (uint32_t)((((2 * c + hiA) ^ swA) << 4)));
            uint32_t gb = (uint32_t)((((2 * c + hiB) ^ swB) << 4));
#pragma unroll
            for (int p = 0; p < 4; p++) {
                uint4 Kf;
                ldsm4(Kf, kB_base[p] + ksb + gb);
                mma8(sacc[2 * p],     Qf.x, Qf.y, Qf.z, Qf.w, Kf.x, Kf.y);
                mma8(sacc[2 * p + 1], Qf.x, Qf.y, Qf.z, Qf.w, Kf.z, Kf.w);
            }
        }
        if (kt >= 2 * qb) {
#pragma unroll
            for (int ni = 0; ni < 8; ni++)
#pragma unroll
                for (int j = 0; j < 4; j++) {
                    int col = k0 + ni * 8 + 2 * tig + (j & 1);
                    int row = q0 + rb0 + g + ((j >> 1) << 3);
                    if (col > row) sacc[ni][j] = -1e30f;
                }
        }
        // online softmax + P staging
#pragma unroll
        for (int rr = 0; rr < 2; rr++) {
            float mx = -1e30f;
#pragma unroll
            for (int ni = 0; ni < 8; ni++)
                mx = fmaxf(mx, fmaxf(sacc[ni][rr * 2], sacc[ni][rr * 2 + 1]));
            mx = fmaxf(mx, __shfl_xor_sync(0xffffffffu, mx, 1));
            mx = fmaxf(mx, __shfl_xor_sync(0xffffffffu, mx, 2));
            float mnew = fmaxf(mrow[rr], mx);
            float corr = __expf(mrow[rr] - mnew);
            float rs = 0.f;
#pragma unroll
            for (int ni = 0; ni < 8; ni++) {
                float p0 = __expf(sacc[ni][rr * 2] - mnew);
                float p1 = __expf(sacc[ni][rr * 2 + 1] - mnew);
                sacc[ni][rr * 2] = p0;
                sacc[ni][rr * 2 + 1] = p1;
                rs += p0 + p1;
            }
            rs += __shfl_xor_sync(0xffffffffu, rs, 1);
            rs += __shfl_xor_sync(0xffffffffu, rs, 2);
            lrow[rr] = lrow[rr] * corr + rs;
            mrow[rr] = mnew;
#pragma unroll
            for (int ni = 0; ni < 16; ni++) {
                O[ni][rr * 2] *= corr;
                O[ni][rr * 2 + 1] *= corr;
            }
            int prow = rb0 + g + rr * 8;
            int psw = prow & 7;
            uint32_t* Pr = sm + 49152 + prow * 64;
#pragma unroll
            for (int ni = 0; ni < 8; ni++) {
                int jg = 2 * ni + (tig >> 1);
                uint2 pv = make_uint2(f2tf(sacc[ni][rr * 2]), f2tf(sacc[ni][rr * 2 + 1]));
                *(uint2*)&Pr[((jg ^ psw) << 2) + (tig & 1) * 2] = pv;
            }
        }
        __syncwarp();
        // O += P V
#pragma unroll
        for (int c = 0; c < 8; c++) {
            uint4 Pf;
            ldsm4(Pf, pA_base + (uint32_t)((((2 * c + hiA) ^ swA) << 4)));
            uint32_t gb = (uint32_t)((((2 * c + hiB) ^ swB) << 4));
#pragma unroll
            for (int p = 0; p < 8; p++) {
                uint4 Vf;
                ldsm4(Vf, vB_base[p] + ksb + gb);
                mma8(O[2 * p],     Pf.x, Pf.y, Pf.z, Pf.w, Vf.x, Vf.y);
                mma8(O[2 * p + 1], Pf.x, Pf.y, Pf.z, Pf.w, Vf.z, Vf.w);
            }
        }
    }

    // epilogue (rounded for the O-projection cp.async consumer)
    float* Ob = g_attn + ((size_t)(b * NQ + h)) * SEQ * HD;
#pragma unroll
    for (int rr = 0; rr < 2; rr++) {
        float inv = 1.f / lrow[rr];
        int r = q0 + rb0 + g + rr * 8;
#pragma unroll
        for (int ni = 0; ni < 16; ni++) {
            float2 o = make_float2(__uint_as_float(f2tf(O[ni][rr * 2] * inv)),
                                   __uint_as_float(f2tf(O[ni][rr * 2 + 1] * inv)));
            *(float2*)&Ob[(size_t)r * HD + ni * 8 + 2 * tig] = o;
        }
    }
}

// ---------------- launch ------------------------------------------------------
extern "C" void kernel_launch(void* const* d_in, const int* in_sizes, int n_in,
                              void* d_out, int out_size) {
    const float* x  = (const float*)d_in[0];
    const float* Wq = (const float*)d_in[1];
    const float* Wk = (const float*)d_in[2];
    const float* Wv = (const float*)d_in[3];
    const float* Wo = (const float*)d_in[4];
    const float* qA = (const float*)d_in[5];
    const float* qB = (const float*)d_in[6];
    const float* kA = (const float*)d_in[7];
    const float* kB = (const float*)d_in[8];
    const float* vA = (const float*)d_in[9];
    const float* vB = (const float*)d_in[10];
    const float* oA = (const float*)d_in[11];
    const float* oB = (const float*)d_in[12];
    float* out = (float*)d_out;

    cudaFuncSetAttribute(gemm3_kernel<0>, cudaFuncAttributeMaxDynamicSharedMemorySize, GEMM_SMEM);
    cudaFuncSetAttribute(gemm3_kernel<1>, cudaFuncAttributeMaxDynamicSharedMemorySize, GEMM_SMEM);
    cudaFuncSetAttribute(flash_kernel, cudaFuncAttributeMaxDynamicSharedMemorySize, FL_SMEM);

    rope_table_kernel<<<512, 256>>>();
    convert_all_kernel<<<(5242880 + 255) / 256, 256>>>(x, Wq, Wk, Wv, Wo);
    lora_down_qkv_kernel<<<MROWS, 256>>>(x, qA, kA, vA);

    gemm3_kernel<0><<<dim3(32, 32), 256, GEMM_SMEM>>>(qB, kB, vB, nullptr);

    flash_kernel<<<dim3(SEQ / 128, BATCH * NQ), 256, FL_SMEM>>>();

    lora_down_o_kernel<<<MROWS, 256>>>(oA);
    gemm3_kernel<1><<<dim3(16, 32), 256, GEMM_SMEM>>>(oB, nullptr, nullptr, out);
}